// round 17
// baseline (speedup 1.0000x reference)
#include <cuda_runtime.h>
#include <cuda_bf16.h>
#include <cstdint>

// Soft decision tree, DEPTH=8, 32 feats, 10 classes, B=131072.
// P(leaf) = (prod e over right edges) / (prod (1+e) over path), e = exp(x[f]-t).
// E[f,s] = exp(x[f,s]) staged in shared; node eval = one FMUL (e = E*c).
// BT=128, 2 samples/thread, 4-way subtree split (quarter==warp), combined rcp
// at depth-6. This round: FFMA-folded leaf accumulate, sibling-packed inner
// params (float4 per child pair), balanced 128-thread epilogue.

#define DEPTH   8
#define N_FEAT  32
#define N_CLS   10
#define BT      128               // threads per block
#define SPB     64                // samples per block (32 pairs x 4 quarter-warps)
#define NPAIR   32
#define PADF    66                // padded floats per feature row

#define LOG2E 1.4426950408889634f

__device__ __forceinline__ float ex2f(float z) {
    float e; asm("ex2.approx.f32 %0, %1;" : "=f"(e) : "f"(z)); return e;
}
__device__ __forceinline__ float rcpf(float d) {
    float r; asm("rcp.approx.f32 %0, %1;" : "=f"(r) : "f"(d)); return r;
}
__device__ __forceinline__ float2 lds2(const char* p) { return *(const float2*)p; }

// Depth-6 handler (tree depth 6 node + both depth-7 children). One rcp per
// sample serves both children: r = rcp(DL*DR); 1/DL = r*DR; 1/DR = r*DL.
// Leaf accumulate is FFMA-folded: acc = fma(N, i, acc) / fma(N, i*e, acc).
// Packed records: r0 = {c6, off6, cL, offL}, r1 = {cR, offR, -, -}.
template <int j>
struct D6 {
    static __device__ __forceinline__ void run(float Na, float Da, float Nb, float Db,
                                               const char* xb, char* sb,
                                               const float4* d6r, const uint4* pk) {
        float4 r0 = d6r[2 * j];                         // broadcast LDS.128
        float4 r1 = d6r[2 * j + 1];                     // broadcast LDS.128

        float2 x6 = lds2(xb + __float_as_int(r0.y));
        float e6a = x6.x * r0.x;
        float e6b = x6.y * r0.x;
        float D6a = fmaf(Da, e6a, Da);
        float D6b = fmaf(Db, e6b, Db);
        float NRa = Na * e6a;
        float NRb = Nb * e6b;

        float2 xL = lds2(xb + __float_as_int(r0.w));
        float eLa = xL.x * r0.z;
        float eLb = xL.y * r0.z;
        float DLa = fmaf(D6a, eLa, D6a);
        float DLb = fmaf(D6b, eLb, D6b);

        float2 xR = lds2(xb + __float_as_int(r1.y));
        float eRa = xR.x * r1.x;
        float eRb = xR.y * r1.x;
        float DRa = fmaf(D6a, eRa, D6a);
        float DRb = fmaf(D6b, eRb, D6b);

        float ra  = rcpf(DLa * DRa);
        float rb  = rcpf(DLb * DRb);
        float iLa = ra * DRa, iRa = ra * DLa;
        float iLb = rb * DRb, iRb = rb * DLb;
        float iLea = iLa * eLa, iLeb = iLb * eLb;       // i*e pre-merge
        float iRea = iRa * eRa, iReb = iRb * eRb;

        uint4 k = pk[j];                                // broadcast LDS.128
        {
            float2* a = (float2*)(sb + k.x);            // leaf 4j   : N * iL
            float2 v = *a;
            v.x = fmaf(Na, iLa, v.x); v.y = fmaf(Nb, iLb, v.y);
            *a = v;
        }
        {
            float2* a = (float2*)(sb + k.y);            // leaf 4j+1 : N * iL*eL
            float2 v = *a;
            v.x = fmaf(Na, iLea, v.x); v.y = fmaf(Nb, iLeb, v.y);
            *a = v;
        }
        {
            float2* a = (float2*)(sb + k.z);            // leaf 4j+2 : NR * iR
            float2 v = *a;
            v.x = fmaf(NRa, iRa, v.x); v.y = fmaf(NRb, iRb, v.y);
            *a = v;
        }
        {
            float2* a = (float2*)(sb + k.w);            // leaf 4j+3 : NR * iR*eR
            float2 v = *a;
            v.x = fmaf(NRa, iRea, v.x); v.y = fmaf(NRb, iReb, v.y);
            *a = v;
        }
    }
};

// Inner walk over local depths 0..3 (tree depths 2..5). Each node receives its
// own (c, off) — loaded by its PARENT from a packed sibling-pair float4.
// pairs[(1<<ld)-1 + j] = {cL, offL, cR, offR} for children of node (ld, j).
template <int ld, int j>
struct Walk {
    static __device__ __forceinline__ void run(float Na, float Da, float Nb, float Db,
                                               float c, int off,
                                               const char* xb, char* sb,
                                               const float4* pairs,
                                               const float4* d6r, const uint4* pk) {
        float2 xv = lds2(xb + off);
        float ea = xv.x * c;
        float eb = xv.y * c;
        float Dna = fmaf(Da, ea, Da);
        float Dnb = fmaf(Db, eb, Db);
        float4 pc = pairs[(1 << ld) - 1 + j];           // children's params
        Walk<ld + 1, 2 * j>::run(Na, Dna, Nb, Dnb,
                                 pc.x, __float_as_int(pc.y), xb, sb, pairs, d6r, pk);
        Walk<ld + 1, 2 * j + 1>::run(Na * ea, Dna, Nb * eb, Dnb,
                                 pc.z, __float_as_int(pc.w), xb, sb, pairs, d6r, pk);
    }
};

// Local depth 3 == tree depth 5: children are the depth-6 handlers.
template <int j>
struct Walk<3, j> {
    static __device__ __forceinline__ void run(float Na, float Da, float Nb, float Db,
                                               float c, int off,
                                               const char* xb, char* sb,
                                               const float4* pairs,
                                               const float4* d6r, const uint4* pk) {
        float2 xv = lds2(xb + off);
        float ea = xv.x * c;
        float eb = xv.y * c;
        float Dna = fmaf(Da, ea, Da);
        float Dnb = fmaf(Db, eb, Db);
        D6<2 * j>::run(Na, Dna, Nb, Dnb, xb, sb, d6r, pk);
        D6<2 * j + 1>::run(Na * ea, Dna, Nb * eb, Dnb, xb, sb, d6r, pk);
    }
};

__global__ void __launch_bounds__(BT, 10)
dt_kernel(const float* __restrict__ x,
          const float* __restrict__ thr,
          const int*   __restrict__ feats,
          const int*   __restrict__ cls,
          float* __restrict__ out) {
    __shared__ __align__(16) float    xs[N_FEAT * PADF];      // 8.25 KB: E[f,s]
    __shared__ __align__(16) float    sacc[4 * N_CLS * SPB];  // 10 KB
    __shared__ __align__(8)  float2   s_top[3];               // tree depths 0,1
    __shared__ __align__(8)  float2   s_root[4];              // depth-2 node per quarter
    __shared__ __align__(16) float4   s_pairs[4 * 7];         // sibling pairs d3..d5
    __shared__ __align__(16) float4   s_d6[64 * 2];           // 2 KB (d6+d7 params)
    __shared__ __align__(16) uint4    s_pk[64];               // 1 KB leaf offsets

    const int tid = threadIdx.x;
    const int bs  = blockIdx.x * SPB;
    const int q   = tid >> 5;              // quarter == warp index
    const int pr  = tid & (NPAIR - 1);     // sample-pair index (lane)

    // ---- per-block param prep: node constant c = exp(-t) ----
    if (tid < 3) {
        s_top[tid] = make_float2(ex2f(-thr[tid] * LOG2E),
                                 __int_as_float(feats[tid] * PADF * 4));
    }
    if (tid < 4) {                         // depth-2 roots (global nodes 3..6)
        s_root[tid] = make_float2(ex2f(-thr[3 + tid] * LOG2E),
                                  __int_as_float(feats[3 + tid] * PADF * 4));
    }
    if (tid < 4 * 7) {                     // 28 sibling-pair records
        int qq = tid / 7;
        int i  = tid - qq * 7;             // pair-tree index 0..6 (level order)
        int lp = 31 - __clz(i + 1);        // 0..2 -> children local depth lp+1
        int jp = i + 1 - (1 << lp);
        int dn = lp + 1;                   // local depth of the two child nodes
        int g0 = ((1 << (dn + 2)) - 1) + qq * (1 << dn) + 2 * jp;  // left child
        s_pairs[tid] = make_float4(ex2f(-thr[g0] * LOG2E),
                                   __int_as_float(feats[g0] * PADF * 4),
                                   ex2f(-thr[g0 + 1] * LOG2E),
                                   __int_as_float(feats[g0 + 1] * PADF * 4));
    }
    {                                      // 128 float4 d6 records
        int d6 = tid >> 1;                 // global in-level d6 index 0..63
        int w  = tid & 1;
        if (w == 0) {
            int g6 = 63 + d6;              // depth-6 node
            int gL = 127 + 2 * d6;         // left d7 child
            s_d6[tid] = make_float4(ex2f(-thr[g6] * LOG2E),
                                    __int_as_float(feats[g6] * PADF * 4),
                                    ex2f(-thr[gL] * LOG2E),
                                    __int_as_float(feats[gL] * PADF * 4));
        } else {
            int gR = 128 + 2 * d6;         // right d7 child
            s_d6[tid] = make_float4(ex2f(-thr[gR] * LOG2E),
                                    __int_as_float(feats[gR] * PADF * 4),
                                    0.f, 0.f);
        }
    }
    if (tid < 64) {                        // leaf class byte-offsets per d6
        int lb = tid * 4;
        s_pk[tid] = make_uint4((uint32_t)cls[lb + 0] * (SPB * 4),
                               (uint32_t)cls[lb + 1] * (SPB * 4),
                               (uint32_t)cls[lb + 2] * (SPB * 4),
                               (uint32_t)cls[lb + 3] * (SPB * 4));
    }

    // ---- stage E = exp(x): 64 samples x 32 feats, coalesced LDG.128 + ex2 ----
#pragma unroll
    for (int k = 0; k < (SPB * N_FEAT / 4) / BT; k++) {
        int idx = tid + k * BT;
        int s   = idx >> 3;
        int c4  = idx & 7;
        float4 v = reinterpret_cast<const float4*>(x + (size_t)(bs + s) * N_FEAT)[c4];
        xs[(c4 * 4 + 0) * PADF + s] = ex2f(v.x * LOG2E);
        xs[(c4 * 4 + 1) * PADF + s] = ex2f(v.y * LOG2E);
        xs[(c4 * 4 + 2) * PADF + s] = ex2f(v.z * LOG2E);
        xs[(c4 * 4 + 3) * PADF + s] = ex2f(v.w * LOG2E);
    }

    char* sb = (char*)sacc + q * (N_CLS * SPB * 4) + 8 * pr;
#pragma unroll
    for (int c = 0; c < N_CLS; c++)
        *(float2*)(sb + c * (SPB * 4)) = make_float2(0.f, 0.f);

    __syncthreads();

    const char* xb = (const char*)xs + 8 * pr;
    const float4* pairs = s_pairs + q * 7;
    const float4* d6r   = s_d6 + q * 32;   // 16 d6 records x2 per quarter
    const uint4*  pk    = s_pk + q * 16;

    // replicated top 2 levels
    float2 p0  = s_top[0];
    float2 xv0 = lds2(xb + __float_as_int(p0.y));
    float e0a = xv0.x * p0.x;
    float e0b = xv0.y * p0.x;
    float Da = e0a + 1.f;
    float Db = e0b + 1.f;
    float Na = (q & 2) ? e0a : 1.0f;
    float Nb = (q & 2) ? e0b : 1.0f;

    float2 p1  = s_top[1 + (q >> 1)];
    float2 xv1 = lds2(xb + __float_as_int(p1.y));
    float e1a = xv1.x * p1.x;
    float e1b = xv1.y * p1.x;
    Da = fmaf(Da, e1a, Da);
    Db = fmaf(Db, e1b, Db);
    if (q & 1) { Na *= e1a; Nb *= e1b; }

    // quarter subtree root (tree depth 2)
    float2 pr2 = s_root[q];
    Walk<0, 0>::run(Na, Da, Nb, Db, pr2.x, __float_as_int(pr2.y),
                    xb, sb, pairs, d6r, pk);

    __syncthreads();

    // combine 4 quarter-accumulators; 128 threads, 5 classes each
    {
        int h2 = tid >> 6;                 // class half: 0 -> 0..4, 1 -> 5..9
        int s  = tid & 63;
        float a[5];
#pragma unroll
        for (int cc = 0; cc < 5; cc++) {
            int c = h2 * 5 + cc;
            float v = 0.f;
#pragma unroll
            for (int qq = 0; qq < 4; qq++)
                v += sacc[qq * (N_CLS * SPB) + c * SPB + s];
            a[cc] = v;
        }
        float* o = out + (size_t)(bs + s) * N_CLS + h2 * 5;
#pragma unroll
        for (int cc = 0; cc < 5; cc++) o[cc] = a[cc];
    }
}

extern "C" void kernel_launch(void* const* d_in, const int* in_sizes, int n_in,
                              void* d_out, int out_size) {
    const float* x     = (const float*)d_in[0];
    const float* thr   = (const float*)d_in[1];
    const int*   feats = (const int*)d_in[2];
    const int*   cls   = (const int*)d_in[3];
    float*       out   = (float*)d_out;

    const int B = in_sizes[0] / N_FEAT;

    dt_kernel<<<B / SPB, BT>>>(x, thr, feats, cls, out);
}